// round 4
// baseline (speedup 1.0000x reference)
#include <cuda_runtime.h>
#include <cuda_fp16.h>
#include <cstddef>
#include <cstdint>

#define NN 50000
#define EE 1600000
#define QQ 16
#define EPSV 1e-8f

// Scratch (allocation-free rule: __device__ globals)
// temp2 stored as fp16: 32 B per edge -> 51.2 MB per buffer; both fit in L2.
__device__ __align__(16) __half2 g_t2a[(size_t)EE * 8];
__device__ __align__(16) __half2 g_t2b[(size_t)EE * 8];
__device__ float g_accA[NN * QQ];   // ping-pong marg accumulators
__device__ float g_accB[NN * QQ];

// Packed f32x2 helpers (sm_100+; ptxas never emits FFMA2 from C++)
#define FFMA2(d, a, b, c) \
    asm("fma.rn.f32x2 %0, %1, %2, %3;" : "=l"(d) : "l"(a), "l"(b), "l"(c))
#define PACK2(d, lo, hi) \
    asm("mov.b64 %0, {%1, %2};" : "=l"(d) : "f"(lo), "f"(hi))
#define UNPACK2(lo, hi, s) \
    asm("mov.b64 {%0, %1}, %2;" : "=f"(lo), "=f"(hi) : "l"(s))

// ---------------------------------------------------------------------------
// Fused edge kernel, 1 edge per thread, register-lean for occupancy.
// FIRST : cav from input tensor (no softmax), inv = 1.
// !FIRST: raw = exp(marg[a1_src] - t2_cur[indice] - mx); normalization folded
//         into the epilogue (matmul on unnormalized exp, then *inv).
// LAST  : skip the t2_next store (step-5 temp2 feeds only the reduction).
// marg is the COMPLETED accumulator of the previous pass (already holds
// field + segment_sum); accum is pre-seeded with field via memcpy.
// ---------------------------------------------------------------------------
template <bool FIRST, bool LAST>
__global__ void __launch_bounds__(256, 4)
edge_kernel(const float* __restrict__ cav_in,
            const float* __restrict__ marg,
            const __half2* __restrict__ t2_cur,
            __half2* __restrict__ t2_next,
            const int* __restrict__ a1_src,
            const int* __restrict__ indice,
            const int* __restrict__ edge_dst,
            const float* __restrict__ Cmat,
            float* __restrict__ accum)
{
    __shared__ __align__(16) float Cs[QQ][QQ];
    const int t = threadIdx.x;
    if (t < (QQ * QQ) / 4) {
        ((float4*)&Cs[0][0])[t] = ((const float4*)Cmat)[t];
    }
    __syncthreads();

    const int e = blockIdx.x * blockDim.x + t;   // grid exact: EE/256 blocks
    const int d = __ldcs(edge_dst + e);          // front-batch index loads

    float r[QQ];
    float inv = 1.0f;

    if (FIRST) {
        const float4* cp = (const float4*)(cav_in + (size_t)e * QQ);
#pragma unroll
        for (int g = 0; g < 4; g++) {
            float4 v = __ldcs(cp + g);
            r[4*g+0]=v.x; r[4*g+1]=v.y; r[4*g+2]=v.z; r[4*g+3]=v.w;
        }
    } else {
        const int s = __ldcs(a1_src + e);
        const int j = __ldcs(indice + e);
        const float4* mp = (const float4*)(marg + (size_t)s * QQ);
        const uint4*  tp = (const uint4*)(t2_cur + (size_t)j * 8);
        uint4 ua = tp[0];
        uint4 ub = tp[1];
        const __half2* ha = (const __half2*)&ua;
        const __half2* hb = (const __half2*)&ub;
#pragma unroll
        for (int g = 0; g < 2; g++) {
            float4 m = mp[g];
            float2 t0 = __half22float2(ha[2*g+0]);
            float2 t1 = __half22float2(ha[2*g+1]);
            r[4*g+0]=m.x-t0.x; r[4*g+1]=m.y-t0.y; r[4*g+2]=m.z-t1.x; r[4*g+3]=m.w-t1.y;
        }
#pragma unroll
        for (int g = 0; g < 2; g++) {
            float4 m = mp[2+g];
            float2 t0 = __half22float2(hb[2*g+0]);
            float2 t1 = __half22float2(hb[2*g+1]);
            r[8+4*g+0]=m.x-t0.x; r[8+4*g+1]=m.y-t0.y; r[8+4*g+2]=m.z-t1.x; r[8+4*g+3]=m.w-t1.y;
        }
        float mx = r[0];
#pragma unroll
        for (int q = 1; q < QQ; q++) mx = fmaxf(mx, r[q]);
        float s2 = 0.0f;
#pragma unroll
        for (int q = 0; q < QQ; q++) { r[q] = __expf(r[q] - mx); s2 += r[q]; }
        inv = 1.0f / s2;
    }

    // acc = r @ C (packed f32x2)
    unsigned long long acc[8];
    {
        unsigned long long z; PACK2(z, 0.0f, 0.0f);
#pragma unroll
        for (int j2 = 0; j2 < 8; j2++) acc[j2] = z;
    }
    uint32_t cs_base = (uint32_t)__cvta_generic_to_shared(&Cs[0][0]);
#pragma unroll
    for (int k = 0; k < QQ; k++) {
        unsigned long long c0, c1, c2, c3, c4, c5, c6, c7;
        uint32_t row = cs_base + k * 64;
        asm volatile("ld.shared.v2.u64 {%0,%1}, [%2];"    : "=l"(c0), "=l"(c1) : "r"(row));
        asm volatile("ld.shared.v2.u64 {%0,%1}, [%2+16];" : "=l"(c2), "=l"(c3) : "r"(row));
        asm volatile("ld.shared.v2.u64 {%0,%1}, [%2+32];" : "=l"(c4), "=l"(c5) : "r"(row));
        asm volatile("ld.shared.v2.u64 {%0,%1}, [%2+48];" : "=l"(c6), "=l"(c7) : "r"(row));
        unsigned long long kk;
        PACK2(kk, r[k], r[k]);
        FFMA2(acc[0], kk, c0, acc[0]);
        FFMA2(acc[1], kk, c1, acc[1]);
        FFMA2(acc[2], kk, c2, acc[2]);
        FFMA2(acc[3], kk, c3, acc[3]);
        FFMA2(acc[4], kk, c4, acc[4]);
        FFMA2(acc[5], kk, c5, acc[5]);
        FFMA2(acc[6], kk, c6, acc[6]);
        FFMA2(acc[7], kk, c7, acc[7]);
    }

    // epilogue: o = log(acc*inv + eps) -> fp16 store + fp32 red into accum
    unsigned long long eps2, iv2;
    PACK2(eps2, EPSV, EPSV);
    PACK2(iv2, inv, inv);

    float o[QQ];
#pragma unroll
    for (int j2 = 0; j2 < 8; j2++) {
        unsigned long long v;
        FFMA2(v, acc[j2], iv2, eps2);
        float a, b;
        UNPACK2(a, b, v);
        o[2*j2]   = __logf(a);
        o[2*j2+1] = __logf(b);
    }

    if (!LAST) {
        __align__(16) __half2 hh[8];
#pragma unroll
        for (int p = 0; p < 8; p++) hh[p] = __floats2half2_rn(o[2*p], o[2*p+1]);
        uint4* wp = (uint4*)(t2_next + (size_t)e * 8);
        wp[0] = ((uint4*)hh)[0];
        wp[1] = ((uint4*)hh)[1];
    }

    float* ap = accum + (size_t)d * QQ;
#pragma unroll
    for (int g = 0; g < 4; g++) {
        asm volatile("red.global.add.v4.f32 [%0], {%1,%2,%3,%4};"
                     :: "l"(ap + 4*g), "f"(o[4*g]), "f"(o[4*g+1]),
                        "f"(o[4*g+2]), "f"(o[4*g+3]) : "memory");
    }
}

// out = log_softmax(marg, axis=1)
__global__ void __launch_bounds__(256)
out_kernel(const float* __restrict__ marg, float* __restrict__ out)
{
    const int n = blockIdx.x * blockDim.x + threadIdx.x;
    if (n >= NN) return;
    float x[QQ];
    const float4* mp = (const float4*)(marg + (size_t)n * QQ);
#pragma unroll
    for (int g = 0; g < 4; g++) {
        float4 v = mp[g];
        x[4*g]=v.x; x[4*g+1]=v.y; x[4*g+2]=v.z; x[4*g+3]=v.w;
    }
    float mx = x[0];
#pragma unroll
    for (int q = 1; q < QQ; q++) mx = fmaxf(mx, x[q]);
    float s = 0.0f;
#pragma unroll
    for (int q = 0; q < QQ; q++) s += __expf(x[q] - mx);
    const float lse = mx + __logf(s);
    float4* op = (float4*)(out + (size_t)n * QQ);
#pragma unroll
    for (int g = 0; g < 4; g++)
        op[g] = make_float4(x[4*g]-lse, x[4*g+1]-lse, x[4*g+2]-lse, x[4*g+3]-lse);
}

extern "C" void kernel_launch(void* const* d_in, const int* in_sizes, int n_in,
                              void* d_out, int out_size)
{
    // metadata order: marg_i(unused), cav_ij, C, field_i, edge_dst, a1_src, indice_ij
    const float* cav_ij   = (const float*)d_in[1];
    const float* Cmat     = (const float*)d_in[2];
    const float* field_i  = (const float*)d_in[3];
    const int*   edge_dst = (const int*)d_in[4];
    const int*   a1_src   = (const int*)d_in[5];
    const int*   indice   = (const int*)d_in[6];
    float*       out      = (float*)d_out;

    float *accA, *accB;
    __half2 *t2a, *t2b;
    cudaGetSymbolAddress((void**)&accA, g_accA);
    cudaGetSymbolAddress((void**)&accB, g_accB);
    cudaGetSymbolAddress((void**)&t2a,  g_t2a);
    cudaGetSymbolAddress((void**)&t2b,  g_t2b);

    const size_t NB_BYTES = (size_t)NN * QQ * sizeof(float);
    const int EB = 256;
    const int EG = EE / EB;              // 6250 exact
    const int OG = (NN + 255) / 256;

    // pass 1: cav from input; red into accA (pre-seeded with field)
    cudaMemcpyAsync(accA, field_i, NB_BYTES, cudaMemcpyDeviceToDevice);
    edge_kernel<true, false><<<EG, EB>>>(cav_ij, nullptr, nullptr, t2a,
                                         a1_src, indice, edge_dst, Cmat, accA);

    // passes 2..4: marg = completed accumulator of previous pass
    cudaMemcpyAsync(accB, field_i, NB_BYTES, cudaMemcpyDeviceToDevice);
    edge_kernel<false, false><<<EG, EB>>>(nullptr, accA, t2a, t2b,
                                          a1_src, indice, edge_dst, Cmat, accB);

    cudaMemcpyAsync(accA, field_i, NB_BYTES, cudaMemcpyDeviceToDevice);
    edge_kernel<false, false><<<EG, EB>>>(nullptr, accB, t2b, t2a,
                                          a1_src, indice, edge_dst, Cmat, accA);

    cudaMemcpyAsync(accB, field_i, NB_BYTES, cudaMemcpyDeviceToDevice);
    edge_kernel<false, false><<<EG, EB>>>(nullptr, accA, t2a, t2b,
                                          a1_src, indice, edge_dst, Cmat, accB);

    // pass 5: no t2 store needed
    cudaMemcpyAsync(accA, field_i, NB_BYTES, cudaMemcpyDeviceToDevice);
    edge_kernel<false, true><<<EG, EB>>>(nullptr, accB, t2b, nullptr,
                                         a1_src, indice, edge_dst, Cmat, accA);

    out_kernel<<<OG, 256>>>(accA, out);
}

// round 7
// speedup vs baseline: 1.1339x; 1.1339x over previous
#include <cuda_runtime.h>
#include <cuda_fp16.h>
#include <cstddef>
#include <cstdint>

#define NN 50000
#define EE 1600000
#define QQ 16
#define EPSV 1e-8f
#define WARPS 8

// Scratch (allocation-free rule: __device__ globals)
// temp2 stored as fp16: 32 B per edge; both ping-pong buffers fit in L2.
__device__ __align__(16) __half2 g_t2a[(size_t)EE * 8];
__device__ __align__(16) __half2 g_t2b[(size_t)EE * 8];
__device__ float g_accA[NN * QQ];   // ping-pong marg accumulators
__device__ float g_accB[NN * QQ];

__device__ __forceinline__ uint32_t pack_h2(float lo, float hi) {
    __half2 h = __floats2half2_rn(lo, hi);
    uint32_t u;
    asm("mov.b32 %0, %1;" : "=r"(u) : "r"(*(uint32_t*)&h));
    return u;
}

// split x into fp16 hi + fp16 lo (x ~= hi + lo to ~2^-21 rel)
__device__ __forceinline__ void split_f16(float x, float& hi, float& lo) {
    __half h = __float2half_rn(x);
    hi = __half2float(h);
    lo = x - hi;
}

// ---------------------------------------------------------------------------
// Fused edge kernel, warp-cooperative tensor-core matmul with split-fp16
// (Markidis) precision recovery: D = Ah*Ch + Ah*Cl + Al*Ch (fp32 accum).
// Per warp: 32 consecutive edges.
//   Phase 1 (lane = edge): gather marg[a1_src]/t2[indice], softmax in regs,
//            split exp row into hi/lo fp16 tiles in per-warp smem.
//   Phase 2: per 16-edge tile: 2x ldmatrix.x4 (hi, lo) -> 6x mma m16n8k16;
//            epilogue o = log(d*inv + eps), fp16 t2 store + red.v2 into accum.
// FIRST: cav comes from input (no softmax), inv = 1.
// LAST : skip the t2 store.
// ---------------------------------------------------------------------------
template <bool FIRST, bool LAST>
__global__ void __launch_bounds__(256)
edge_kernel(const float* __restrict__ cav_in,
            const float* __restrict__ marg,
            const __half2* __restrict__ t2_cur,
            __half2* __restrict__ t2_next,
            const int* __restrict__ a1_src,
            const int* __restrict__ indice,
            const int* __restrict__ edge_dst,
            const float* __restrict__ Cmat,
            float* __restrict__ accum)
{
    // per-warp exp tiles: [hi|lo], each 32 rows x 16 halves (32 B rows)
    __shared__ __align__(16) __half2 sExp[WARPS][2][32 * 8];

    const int lane = threadIdx.x & 31;
    const int w    = threadIdx.x >> 5;
    const int i4   = lane & 3;        // col-pair selector
    const int g8   = lane >> 2;       // row-in-8 selector
    const int e    = blockIdx.x * 256 + w * 32 + lane;   // grid exact

    // ---- B fragments: C split hi/lo, loaded once (L2-resident, 1 KB) ----
    // bh0/bh1: cols 0-7 tile, bh2/bh3: cols 8-15 tile; bl* = lo parts.
    uint32_t bh0, bh1, bh2, bh3, bl0, bl1, bl2, bl3;
    {
        const int k0 = 2 * i4;
        float h00,l00,h01,l01, h10,l10,h11,l11;
#pragma unroll
        for (int nb = 0; nb < 2; nb++) {
            const int n = nb * 8 + g8;
            split_f16(Cmat[(k0    ) * QQ + n], h00, l00);
            split_f16(Cmat[(k0 + 1) * QQ + n], h01, l01);
            split_f16(Cmat[(k0 + 8) * QQ + n], h10, l10);
            split_f16(Cmat[(k0 + 9) * QQ + n], h11, l11);
            if (nb == 0) {
                bh0 = pack_h2(h00, h01); bh1 = pack_h2(h10, h11);
                bl0 = pack_h2(l00, l01); bl1 = pack_h2(l10, l11);
            } else {
                bh2 = pack_h2(h00, h01); bh3 = pack_h2(h10, h11);
                bl2 = pack_h2(l00, l01); bl3 = pack_h2(l10, l11);
            }
        }
    }

    // ---- Phase 1: per-lane edge -> hi/lo exp rows in smem ----
    const int dst = __ldcs(edge_dst + e);
    float inv = 1.0f;
    {
        float r[QQ];
        if (FIRST) {
            const float4* cp = (const float4*)(cav_in + (size_t)e * QQ);
#pragma unroll
            for (int g = 0; g < 4; g++) {
                float4 v = __ldcs(cp + g);
                r[4*g+0]=v.x; r[4*g+1]=v.y; r[4*g+2]=v.z; r[4*g+3]=v.w;
            }
        } else {
            const int s = __ldcs(a1_src + e);
            const int j = __ldcs(indice + e);
            const float4* mp = (const float4*)(marg + (size_t)s * QQ);
            const uint4*  tp = (const uint4*)(t2_cur + (size_t)j * 8);
            uint4 ua = tp[0];
            uint4 ub = tp[1];
            const __half2* ha = (const __half2*)&ua;
            const __half2* hb = (const __half2*)&ub;
#pragma unroll
            for (int g = 0; g < 2; g++) {
                float4 m = mp[g];
                float2 t0 = __half22float2(ha[2*g+0]);
                float2 t1 = __half22float2(ha[2*g+1]);
                r[4*g+0]=m.x-t0.x; r[4*g+1]=m.y-t0.y;
                r[4*g+2]=m.z-t1.x; r[4*g+3]=m.w-t1.y;
            }
#pragma unroll
            for (int g = 0; g < 2; g++) {
                float4 m = mp[2+g];
                float2 t0 = __half22float2(hb[2*g+0]);
                float2 t1 = __half22float2(hb[2*g+1]);
                r[8+4*g+0]=m.x-t0.x; r[8+4*g+1]=m.y-t0.y;
                r[8+4*g+2]=m.z-t1.x; r[8+4*g+3]=m.w-t1.y;
            }
            float mx = r[0];
#pragma unroll
            for (int q = 1; q < QQ; q++) mx = fmaxf(mx, r[q]);
            float ss = 0.0f;
#pragma unroll
            for (int q = 0; q < QQ; q++) { r[q] = __expf(r[q] - mx); ss += r[q]; }
            inv = 1.0f / ss;
        }
        // split rows into hi/lo fp16 tiles (2x 2 STS.128)
        __align__(16) __half2 hhi[8], hlo[8];
#pragma unroll
        for (int p = 0; p < 8; p++) {
            float h0, l0, h1, l1;
            split_f16(r[2*p],   h0, l0);
            split_f16(r[2*p+1], h1, l1);
            hhi[p] = __floats2half2_rn(h0, h1);
            hlo[p] = __floats2half2_rn(l0, l1);
        }
        uint4* rp = (uint4*)&sExp[w][0][lane * 8];
        rp[0] = ((uint4*)hhi)[0];
        rp[1] = ((uint4*)hhi)[1];
        uint4* rq = (uint4*)&sExp[w][1][lane * 8];
        rq[0] = ((uint4*)hlo)[0];
        rq[1] = ((uint4*)hlo)[1];
    }
    __syncwarp();

    // ---- Phase 2: two 16-edge tiles ----
    const uint32_t smem_hi = (uint32_t)__cvta_generic_to_shared(&sExp[w][0][0]);
    const uint32_t smem_lo = (uint32_t)__cvta_generic_to_shared(&sExp[w][1][0]);
    const int e_warp0 = blockIdx.x * 256 + w * 32;

#pragma unroll
    for (int T = 0; T < 2; T++) {
        // ldmatrix: sub-tile = lane/8; row (sub&1)*8 + lane%8, 16B chunk sub>>1
        const int sub = lane >> 3;
        const int rin = lane & 7;
        const uint32_t off =
            (uint32_t)((T * 16 + (sub & 1) * 8 + rin) * 32 + (sub >> 1) * 16);
        uint32_t ah0, ah1, ah2, ah3, al0, al1, al2, al3;
        asm volatile("ldmatrix.sync.aligned.m8n8.x4.shared.b16 {%0,%1,%2,%3}, [%4];"
                     : "=r"(ah0), "=r"(ah1), "=r"(ah2), "=r"(ah3)
                     : "r"(smem_hi + off));
        asm volatile("ldmatrix.sync.aligned.m8n8.x4.shared.b16 {%0,%1,%2,%3}, [%4];"
                     : "=r"(al0), "=r"(al1), "=r"(al2), "=r"(al3)
                     : "r"(smem_lo + off));

        float d0[4] = {0.f, 0.f, 0.f, 0.f};
        float d1[4] = {0.f, 0.f, 0.f, 0.f};
#define MMA(D, A0, A1, A2, A3, B0, B1) \
        asm volatile("mma.sync.aligned.m16n8k16.row.col.f32.f16.f16.f32 " \
                     "{%0,%1,%2,%3}, {%4,%5,%6,%7}, {%8,%9}, {%0,%1,%2,%3};" \
                     : "+f"(D[0]), "+f"(D[1]), "+f"(D[2]), "+f"(D[3]) \
                     : "r"(A0), "r"(A1), "r"(A2), "r"(A3), "r"(B0), "r"(B1))
        // n-tile 0: Ah*Ch + Ah*Cl + Al*Ch
        MMA(d0, ah0, ah1, ah2, ah3, bh0, bh1);
        MMA(d0, ah0, ah1, ah2, ah3, bl0, bl1);
        MMA(d0, al0, al1, al2, al3, bh0, bh1);
        // n-tile 1
        MMA(d1, ah0, ah1, ah2, ah3, bh2, bh3);
        MMA(d1, ah0, ah1, ah2, ah3, bl2, bl3);
        MMA(d1, al0, al1, al2, al3, bh2, bh3);
#undef MMA

        // redistribute per-edge inv and dst to the D-fragment rows
        const float invA = __shfl_sync(0xffffffffu, inv, T * 16 + g8);
        const float invB = __shfl_sync(0xffffffffu, inv, T * 16 + 8 + g8);
        const int   dstA = __shfl_sync(0xffffffffu, dst, T * 16 + g8);
        const int   dstB = __shfl_sync(0xffffffffu, dst, T * 16 + 8 + g8);
        const int   eA   = e_warp0 + T * 16 + g8;
        const int   eB   = eA + 8;

        // row A: cols {2i4,2i4+1} from d0[0..1]; cols {8+2i4,8+2i4+1} from d1[0..1]
        float oA0 = __logf(fmaf(d0[0], invA, EPSV));
        float oA1 = __logf(fmaf(d0[1], invA, EPSV));
        float oA2 = __logf(fmaf(d1[0], invA, EPSV));
        float oA3 = __logf(fmaf(d1[1], invA, EPSV));
        // row B (row+8): d0[2..3], d1[2..3]
        float oB0 = __logf(fmaf(d0[2], invB, EPSV));
        float oB1 = __logf(fmaf(d0[3], invB, EPSV));
        float oB2 = __logf(fmaf(d1[2], invB, EPSV));
        float oB3 = __logf(fmaf(d1[3], invB, EPSV));

        if (!LAST) {
            __half2* tA = t2_next + (size_t)eA * 8;
            __half2* tB = t2_next + (size_t)eB * 8;
            tA[i4]     = __floats2half2_rn(oA0, oA1);
            tA[4 + i4] = __floats2half2_rn(oA2, oA3);
            tB[i4]     = __floats2half2_rn(oB0, oB1);
            tB[4 + i4] = __floats2half2_rn(oB2, oB3);
        }

        float* apA = accum + (size_t)dstA * QQ;
        float* apB = accum + (size_t)dstB * QQ;
        asm volatile("red.global.add.v2.f32 [%0], {%1,%2};"
                     :: "l"(apA + 2 * i4),     "f"(oA0), "f"(oA1) : "memory");
        asm volatile("red.global.add.v2.f32 [%0], {%1,%2};"
                     :: "l"(apA + 8 + 2 * i4), "f"(oA2), "f"(oA3) : "memory");
        asm volatile("red.global.add.v2.f32 [%0], {%1,%2};"
                     :: "l"(apB + 2 * i4),     "f"(oB0), "f"(oB1) : "memory");
        asm volatile("red.global.add.v2.f32 [%0], {%1,%2};"
                     :: "l"(apB + 8 + 2 * i4), "f"(oB2), "f"(oB3) : "memory");
    }
}

// out = log_softmax(marg, axis=1)
__global__ void __launch_bounds__(256)
out_kernel(const float* __restrict__ marg, float* __restrict__ out)
{
    const int n = blockIdx.x * blockDim.x + threadIdx.x;
    if (n >= NN) return;
    float x[QQ];
    const float4* mp = (const float4*)(marg + (size_t)n * QQ);
#pragma unroll
    for (int g = 0; g < 4; g++) {
        float4 v = mp[g];
        x[4*g]=v.x; x[4*g+1]=v.y; x[4*g+2]=v.z; x[4*g+3]=v.w;
    }
    float mx = x[0];
#pragma unroll
    for (int q = 1; q < QQ; q++) mx = fmaxf(mx, x[q]);
    float s = 0.0f;
#pragma unroll
    for (int q = 0; q < QQ; q++) s += __expf(x[q] - mx);
    const float lse = mx + __logf(s);
    float4* op = (float4*)(out + (size_t)n * QQ);
#pragma unroll
    for (int g = 0; g < 4; g++)
        op[g] = make_float4(x[4*g]-lse, x[4*g+1]-lse, x[4*g+2]-lse, x[4*g+3]-lse);
}

extern "C" void kernel_launch(void* const* d_in, const int* in_sizes, int n_in,
                              void* d_out, int out_size)
{
    // metadata order: marg_i(unused), cav_ij, C, field_i, edge_dst, a1_src, indice_ij
    const float* cav_ij   = (const float*)d_in[1];
    const float* Cmat     = (const float*)d_in[2];
    const float* field_i  = (const float*)d_in[3];
    const int*   edge_dst = (const int*)d_in[4];
    const int*   a1_src   = (const int*)d_in[5];
    const int*   indice   = (const int*)d_in[6];
    float*       out      = (float*)d_out;

    float *accA, *accB;
    __half2 *t2a, *t2b;
    cudaGetSymbolAddress((void**)&accA, g_accA);
    cudaGetSymbolAddress((void**)&accB, g_accB);
    cudaGetSymbolAddress((void**)&t2a,  g_t2a);
    cudaGetSymbolAddress((void**)&t2b,  g_t2b);

    const size_t NB_BYTES = (size_t)NN * QQ * sizeof(float);
    const int EB = 256;
    const int EG = EE / EB;              // 6250 exact
    const int OG = (NN + 255) / 256;

    // pass 1: cav from input; red into accA (pre-seeded with field)
    cudaMemcpyAsync(accA, field_i, NB_BYTES, cudaMemcpyDeviceToDevice);
    edge_kernel<true, false><<<EG, EB>>>(cav_ij, nullptr, nullptr, t2a,
                                         a1_src, indice, edge_dst, Cmat, accA);

    cudaMemcpyAsync(accB, field_i, NB_BYTES, cudaMemcpyDeviceToDevice);
    edge_kernel<false, false><<<EG, EB>>>(nullptr, accA, t2a, t2b,
                                          a1_src, indice, edge_dst, Cmat, accB);

    cudaMemcpyAsync(accA, field_i, NB_BYTES, cudaMemcpyDeviceToDevice);
    edge_kernel<false, false><<<EG, EB>>>(nullptr, accB, t2b, t2a,
                                          a1_src, indice, edge_dst, Cmat, accA);

    cudaMemcpyAsync(accB, field_i, NB_BYTES, cudaMemcpyDeviceToDevice);
    edge_kernel<false, false><<<EG, EB>>>(nullptr, accA, t2a, t2b,
                                          a1_src, indice, edge_dst, Cmat, accB);

    // pass 5: no t2 store needed
    cudaMemcpyAsync(accA, field_i, NB_BYTES, cudaMemcpyDeviceToDevice);
    edge_kernel<false, true><<<EG, EB>>>(nullptr, accB, t2b, nullptr,
                                         a1_src, indice, edge_dst, Cmat, accA);

    out_kernel<<<OG, 256>>>(accA, out);
}

// round 8
// speedup vs baseline: 1.7460x; 1.5399x over previous
#include <cuda_runtime.h>
#include <cuda_fp16.h>
#include <cstddef>
#include <cstdint>

#define NN 50000
#define EE 1600000
#define QQ 16
#define EPSV 1e-8f

// Scratch (allocation-free rule: __device__ globals)
// temp2 stored as fp16 in fragment-permuted col order: 32 B per edge.
__device__ __align__(16) __half2 g_t2a[(size_t)EE * 8];
__device__ __align__(16) __half2 g_t2b[(size_t)EE * 8];
__device__ float g_accA[NN * QQ];   // ping-pong marg accumulators (permuted)
__device__ float g_accB[NN * QQ];

// permuted position p  <->  natural column
__host__ __device__ constexpr int permcol(int p) {
    return 2 * (p >> 2) + (p & 1) + 8 * ((p >> 1) & 1);
}

__device__ __forceinline__ uint32_t pack_h2(float a, float b) {
    __half2 h = __floats2half2_rn(a, b);
    uint32_t u;
    asm("mov.b32 %0, %1;" : "=r"(u) : "r"(*(uint32_t*)&h));
    return u;
}

// split x into fp16 hi + residual lo
__device__ __forceinline__ void split_f16(float x, float& hi, float& lo) {
    __half h = __float2half_rn(x);
    hi = __half2float(h);
    lo = x - hi;
}

// ---------------------------------------------------------------------------
// Fused edge kernel: quad-cooperative rows, fragment-direct, no smem.
// 4 lanes (i4 = lane&3) own one edge row; each lane holds natural cols
// {2i4, 2i4+1, 2i4+8, 2i4+9} — exactly its m16n8k16 A-fragment slots.
// marg/t2/accum use the matching permuted layout -> single coalesced
// LDG.128 / LDG.64 / STG.64 / red.v4 per row-lane.
// Precision: split-fp16 Markidis (Ah*Ch + Ah*Cl + Al*Ch, fp32 accum).
// ---------------------------------------------------------------------------
template <bool FIRST, bool LAST>
__global__ void __launch_bounds__(256)
edge_kernel(const float* __restrict__ cav_in,
            const float* __restrict__ marg,      // permuted
            const __half2* __restrict__ t2_cur,  // permuted
            __half2* __restrict__ t2_next,       // permuted
            const int* __restrict__ a1_src,
            const int* __restrict__ indice,
            const int* __restrict__ edge_dst,
            const float* __restrict__ Cmat,
            float* __restrict__ accum)           // permuted
{
    const int lane = threadIdx.x & 31;
    const int i4   = lane & 3;
    const int g8   = lane >> 2;
    const int base = blockIdx.x * 256 + (threadIdx.x >> 5) * 32;

    // ---- B fragments: C split hi/lo (verified R7 mapping) ----
    uint32_t bh0, bh1, bh2, bh3, bl0, bl1, bl2, bl3;
    {
        const int k0 = 2 * i4;
        float h00,l00,h01,l01, h10,l10,h11,l11;
#pragma unroll
        for (int nb = 0; nb < 2; nb++) {
            const int n = nb * 8 + g8;
            split_f16(Cmat[(k0    ) * QQ + n], h00, l00);
            split_f16(Cmat[(k0 + 1) * QQ + n], h01, l01);
            split_f16(Cmat[(k0 + 8) * QQ + n], h10, l10);
            split_f16(Cmat[(k0 + 9) * QQ + n], h11, l11);
            if (nb == 0) {
                bh0 = pack_h2(h00, h01); bh1 = pack_h2(h10, h11);
                bl0 = pack_h2(l00, l01); bl1 = pack_h2(l10, l11);
            } else {
                bh2 = pack_h2(h00, h01); bh3 = pack_h2(h10, h11);
                bl2 = pack_h2(l00, l01); bl3 = pack_h2(l10, l11);
            }
        }
    }

#pragma unroll
    for (int T = 0; T < 2; T++) {
        const int eA = base + T * 16 + g8;   // row g8 of this tile
        const int eB = eA + 8;               // row g8+8
        const int dstA = __ldg(edge_dst + eA);
        const int dstB = __ldg(edge_dst + eB);

        // xA/xB: natural cols {2i4, 2i4+1, 2i4+8, 2i4+9} of rows eA/eB
        float xA[4], xB[4];
        float invA = 1.0f, invB = 1.0f;

        if (FIRST) {
            const float2* pA = (const float2*)(cav_in + (size_t)eA * QQ);
            const float2* pB = (const float2*)(cav_in + (size_t)eB * QQ);
            float2 a0 = __ldcs(pA + i4);
            float2 a1 = __ldcs(pA + 4 + i4);
            float2 b0 = __ldcs(pB + i4);
            float2 b1 = __ldcs(pB + 4 + i4);
            xA[0]=a0.x; xA[1]=a0.y; xA[2]=a1.x; xA[3]=a1.y;
            xB[0]=b0.x; xB[1]=b0.y; xB[2]=b1.x; xB[3]=b1.y;
        } else {
            const int sA = __ldg(a1_src + eA), sB = __ldg(a1_src + eB);
            const int jA = __ldg(indice + eA), jB = __ldg(indice + eB);
            // permuted marg: this lane's 4 cols are contiguous 16 B
            float4 mA = __ldg((const float4*)(marg + (size_t)sA * QQ + 4 * i4));
            float4 mB = __ldg((const float4*)(marg + (size_t)sB * QQ + 4 * i4));
            // permuted t2: this lane's 4 halves are contiguous 8 B
            uint2 ta = *(const uint2*)(t2_cur + (size_t)jA * 8 + 2 * i4);
            uint2 tb = *(const uint2*)(t2_cur + (size_t)jB * 8 + 2 * i4);
            float2 fa0 = __half22float2(*(__half2*)&ta.x);
            float2 fa1 = __half22float2(*(__half2*)&ta.y);
            float2 fb0 = __half22float2(*(__half2*)&tb.x);
            float2 fb1 = __half22float2(*(__half2*)&tb.y);
            xA[0]=mA.x-fa0.x; xA[1]=mA.y-fa0.y; xA[2]=mA.z-fa1.x; xA[3]=mA.w-fa1.y;
            xB[0]=mB.x-fb0.x; xB[1]=mB.y-fb0.y; xB[2]=mB.z-fb1.x; xB[3]=mB.w-fb1.y;

            // quad softmax (lanes 4g8..4g8+3 hold the full 16-col row)
            float mxA = fmaxf(fmaxf(xA[0], xA[1]), fmaxf(xA[2], xA[3]));
            float mxB = fmaxf(fmaxf(xB[0], xB[1]), fmaxf(xB[2], xB[3]));
            mxA = fmaxf(mxA, __shfl_xor_sync(0xffffffffu, mxA, 1));
            mxA = fmaxf(mxA, __shfl_xor_sync(0xffffffffu, mxA, 2));
            mxB = fmaxf(mxB, __shfl_xor_sync(0xffffffffu, mxB, 1));
            mxB = fmaxf(mxB, __shfl_xor_sync(0xffffffffu, mxB, 2));
            float sAs = 0.f, sBs = 0.f;
#pragma unroll
            for (int q = 0; q < 4; q++) {
                xA[q] = __expf(xA[q] - mxA); sAs += xA[q];
                xB[q] = __expf(xB[q] - mxB); sBs += xB[q];
            }
            sAs += __shfl_xor_sync(0xffffffffu, sAs, 1);
            sAs += __shfl_xor_sync(0xffffffffu, sAs, 2);
            sBs += __shfl_xor_sync(0xffffffffu, sBs, 1);
            sBs += __shfl_xor_sync(0xffffffffu, sBs, 2);
            invA = 1.0f / sAs;
            invB = 1.0f / sBs;
        }

        // ---- A fragments directly in registers (hi/lo split) ----
        float h0,l0,h1,l1,h2,l2,h3,l3;
        split_f16(xA[0], h0, l0); split_f16(xA[1], h1, l1);
        split_f16(xA[2], h2, l2); split_f16(xA[3], h3, l3);
        uint32_t ah0 = pack_h2(h0, h1), ah2 = pack_h2(h2, h3);
        uint32_t al0 = pack_h2(l0, l1), al2 = pack_h2(l2, l3);
        split_f16(xB[0], h0, l0); split_f16(xB[1], h1, l1);
        split_f16(xB[2], h2, l2); split_f16(xB[3], h3, l3);
        uint32_t ah1 = pack_h2(h0, h1), ah3 = pack_h2(h2, h3);
        uint32_t al1 = pack_h2(l0, l1), al3 = pack_h2(l2, l3);

        float d0[4] = {0.f, 0.f, 0.f, 0.f};
        float d1[4] = {0.f, 0.f, 0.f, 0.f};
#define MMA(D, A0, A1, A2, A3, B0, B1) \
        asm volatile("mma.sync.aligned.m16n8k16.row.col.f32.f16.f16.f32 " \
                     "{%0,%1,%2,%3}, {%4,%5,%6,%7}, {%8,%9}, {%0,%1,%2,%3};" \
                     : "+f"(D[0]), "+f"(D[1]), "+f"(D[2]), "+f"(D[3]) \
                     : "r"(A0), "r"(A1), "r"(A2), "r"(A3), "r"(B0), "r"(B1))
        MMA(d0, ah0, ah1, ah2, ah3, bh0, bh1);
        MMA(d0, ah0, ah1, ah2, ah3, bl0, bl1);
        MMA(d0, al0, al1, al2, al3, bh0, bh1);
        MMA(d1, ah0, ah1, ah2, ah3, bh2, bh3);
        MMA(d1, ah0, ah1, ah2, ah3, bl2, bl3);
        MMA(d1, al0, al1, al2, al3, bh2, bh3);
#undef MMA

        // epilogue: rows eA (d0[0..1], d1[0..1]) and eB (d0[2..3], d1[2..3])
        float oA0 = __logf(fmaf(d0[0], invA, EPSV));   // col 2i4
        float oA1 = __logf(fmaf(d0[1], invA, EPSV));   // col 2i4+1
        float oA2 = __logf(fmaf(d1[0], invA, EPSV));   // col 2i4+8
        float oA3 = __logf(fmaf(d1[1], invA, EPSV));   // col 2i4+9
        float oB0 = __logf(fmaf(d0[2], invB, EPSV));
        float oB1 = __logf(fmaf(d0[3], invB, EPSV));
        float oB2 = __logf(fmaf(d1[2], invB, EPSV));
        float oB3 = __logf(fmaf(d1[3], invB, EPSV));

        if (!LAST) {
            // permuted t2 store: one coalesced 8 B per row-lane
            uint2 vA, vB;
            vA.x = pack_h2(oA0, oA1); vA.y = pack_h2(oA2, oA3);
            vB.x = pack_h2(oB0, oB1); vB.y = pack_h2(oB2, oB3);
            *(uint2*)(t2_next + (size_t)eA * 8 + 2 * i4) = vA;
            *(uint2*)(t2_next + (size_t)eB * 8 + 2 * i4) = vB;
        }

        // permuted accum: contiguous red.v4 per row-lane
        asm volatile("red.global.add.v4.f32 [%0], {%1,%2,%3,%4};"
                     :: "l"(accum + (size_t)dstA * QQ + 4 * i4),
                        "f"(oA0), "f"(oA1), "f"(oA2), "f"(oA3) : "memory");
        asm volatile("red.global.add.v4.f32 [%0], {%1,%2,%3,%4};"
                     :: "l"(accum + (size_t)dstB * QQ + 4 * i4),
                        "f"(oB0), "f"(oB1), "f"(oB2), "f"(oB3) : "memory");
    }
}

// accum = permute(field)   (seeds each pass; replaces memcpy)
__global__ void __launch_bounds__(256)
seed_kernel(const float* __restrict__ field, float* __restrict__ accum)
{
    const int n = blockIdx.x * blockDim.x + threadIdx.x;
    if (n >= NN) return;
    const float4* fp = (const float4*)(field + (size_t)n * QQ);
    float4 v[4] = {fp[0], fp[1], fp[2], fp[3]};
    const float* x = (const float*)v;
    float y[QQ];
#pragma unroll
    for (int p = 0; p < QQ; p++) y[p] = x[permcol(p)];
    float4* op = (float4*)(accum + (size_t)n * QQ);
#pragma unroll
    for (int g = 0; g < 4; g++) op[g] = ((float4*)y)[g];
}

// out = log_softmax(marg) — read permuted, write natural order
__global__ void __launch_bounds__(256)
out_kernel(const float* __restrict__ marg, float* __restrict__ out)
{
    const int n = blockIdx.x * blockDim.x + threadIdx.x;
    if (n >= NN) return;
    const float4* mp = (const float4*)(marg + (size_t)n * QQ);
    float4 v[4] = {mp[0], mp[1], mp[2], mp[3]};
    const float* x = (const float*)v;
    float mx = x[0];
#pragma unroll
    for (int p = 1; p < QQ; p++) mx = fmaxf(mx, x[p]);
    float s = 0.0f;
#pragma unroll
    for (int p = 0; p < QQ; p++) s += __expf(x[p] - mx);
    const float lse = mx + __logf(s);
    float y[QQ];
#pragma unroll
    for (int p = 0; p < QQ; p++) y[permcol(p)] = x[p] - lse;
    float4* op = (float4*)(out + (size_t)n * QQ);
#pragma unroll
    for (int g = 0; g < 4; g++) op[g] = ((float4*)y)[g];
}

extern "C" void kernel_launch(void* const* d_in, const int* in_sizes, int n_in,
                              void* d_out, int out_size)
{
    // metadata order: marg_i(unused), cav_ij, C, field_i, edge_dst, a1_src, indice_ij
    const float* cav_ij   = (const float*)d_in[1];
    const float* Cmat     = (const float*)d_in[2];
    const float* field_i  = (const float*)d_in[3];
    const int*   edge_dst = (const int*)d_in[4];
    const int*   a1_src   = (const int*)d_in[5];
    const int*   indice   = (const int*)d_in[6];
    float*       out      = (float*)d_out;

    float *accA, *accB;
    __half2 *t2a, *t2b;
    cudaGetSymbolAddress((void**)&accA, g_accA);
    cudaGetSymbolAddress((void**)&accB, g_accB);
    cudaGetSymbolAddress((void**)&t2a,  g_t2a);
    cudaGetSymbolAddress((void**)&t2b,  g_t2b);

    const int EB = 256;
    const int EG = EE / EB;              // 6250 exact
    const int NG = (NN + 255) / 256;

    // pass 1: cav from input; red into accA (pre-seeded with permuted field)
    seed_kernel<<<NG, 256>>>(field_i, accA);
    edge_kernel<true, false><<<EG, EB>>>(cav_ij, nullptr, nullptr, t2a,
                                         a1_src, indice, edge_dst, Cmat, accA);

    seed_kernel<<<NG, 256>>>(field_i, accB);
    edge_kernel<false, false><<<EG, EB>>>(nullptr, accA, t2a, t2b,
                                          a1_src, indice, edge_dst, Cmat, accB);

    seed_kernel<<<NG, 256>>>(field_i, accA);
    edge_kernel<false, false><<<EG, EB>>>(nullptr, accB, t2b, t2a,
                                          a1_src, indice, edge_dst, Cmat, accA);

    seed_kernel<<<NG, 256>>>(field_i, accB);
    edge_kernel<false, false><<<EG, EB>>>(nullptr, accA, t2a, t2b,
                                          a1_src, indice, edge_dst, Cmat, accB);

    // pass 5: no t2 store needed
    seed_kernel<<<NG, 256>>>(field_i, accA);
    edge_kernel<false, true><<<EG, EB>>>(nullptr, accB, t2b, nullptr,
                                         a1_src, indice, edge_dst, Cmat, accA);

    out_kernel<<<NG, 256>>>(accA, out);
}

// round 9
// speedup vs baseline: 1.7770x; 1.0177x over previous
#include <cuda_runtime.h>
#include <cuda_fp16.h>
#include <cstddef>
#include <cstdint>

#define NN 50000
#define EE 1600000
#define QQ 16
#define EPSV 1e-8f

// Scratch (allocation-free rule: __device__ globals)
// temp2 stored as fp16 in fragment-permuted col order: 32 B per edge.
__device__ __align__(16) __half2 g_t2a[(size_t)EE * 8];
__device__ __align__(16) __half2 g_t2b[(size_t)EE * 8];
__device__ float g_acc[5][NN * QQ];   // 5 pre-seeded marg accumulators (permuted)

// permuted position p  <->  natural column
__host__ __device__ constexpr int permcol(int p) {
    return 2 * (p >> 2) + (p & 1) + 8 * ((p >> 1) & 1);
}

__device__ __forceinline__ uint32_t pack_h2(float a, float b) {
    __half2 h = __floats2half2_rn(a, b);
    uint32_t u;
    asm("mov.b32 %0, %1;" : "=r"(u) : "r"(*(uint32_t*)&h));
    return u;
}

// split x into fp16 hi + residual lo (scalar, for C setup)
__device__ __forceinline__ void split_f16(float x, float& hi, float& lo) {
    __half h = __float2half_rn(x);
    hi = __half2float(h);
    lo = x - hi;
}

// packed split of a float pair: hi2 = fp16x2(x0,x1); lo2 = fp16x2(residuals)
__device__ __forceinline__ void split2(float x0, float x1,
                                       uint32_t& hi2, uint32_t& lo2) {
    hi2 = pack_h2(x0, x1);
    __half2 h = *(__half2*)&hi2;
    float2 hf = __half22float2(h);
    lo2 = pack_h2(x0 - hf.x, x1 - hf.y);
}

// ---------------------------------------------------------------------------
// Fused edge kernel: quad-cooperative rows, fragment-direct, no smem.
// 4 lanes (i4 = lane&3) own one edge row; lane holds natural cols
// {2i4, 2i4+1, 2i4+8, 2i4+9} = its m16n8k16 A-fragment slots.
// Restructured: phase 1 gathers+softmax+splits ALL 4 rows (both MMA tiles)
// up front for maximum MLP; then 12 MMAs; then both epilogues.
// Precision: split-fp16 Markidis (Ah*Ch + Ah*Cl + Al*Ch, fp32 accum).
// ---------------------------------------------------------------------------
template <bool FIRST, bool LAST>
__global__ void __launch_bounds__(256, 4)
edge_kernel(const float* __restrict__ cav_in,
            const float* __restrict__ marg,      // permuted
            const __half2* __restrict__ t2_cur,  // permuted
            __half2* __restrict__ t2_next,       // permuted
            const int* __restrict__ a1_src,
            const int* __restrict__ indice,
            const int* __restrict__ edge_dst,
            const float* __restrict__ Cmat,
            float* __restrict__ accum)           // permuted
{
    const int lane = threadIdx.x & 31;
    const int i4   = lane & 3;
    const int g8   = lane >> 2;
    const int base = blockIdx.x * 256 + (threadIdx.x >> 5) * 32;

    // ---- B fragments: C split hi/lo (verified R7/R8 mapping) ----
    uint32_t bh0, bh1, bh2, bh3, bl0, bl1, bl2, bl3;
    {
        const int k0 = 2 * i4;
        float h00,l00,h01,l01, h10,l10,h11,l11;
#pragma unroll
        for (int nb = 0; nb < 2; nb++) {
            const int n = nb * 8 + g8;
            split_f16(Cmat[(k0    ) * QQ + n], h00, l00);
            split_f16(Cmat[(k0 + 1) * QQ + n], h01, l01);
            split_f16(Cmat[(k0 + 8) * QQ + n], h10, l10);
            split_f16(Cmat[(k0 + 9) * QQ + n], h11, l11);
            if (nb == 0) {
                bh0 = pack_h2(h00, h01); bh1 = pack_h2(h10, h11);
                bl0 = pack_h2(l00, l01); bl1 = pack_h2(l10, l11);
            } else {
                bh2 = pack_h2(h00, h01); bh3 = pack_h2(h10, h11);
                bl2 = pack_h2(l00, l01); bl3 = pack_h2(l10, l11);
            }
        }
    }

    // ---- Phase 1: all 4 rows (tiles T=0: rows 0,1; T=1: rows 2,3) ----
    // row r -> edge base + r*8 + g8.  r even = "A" slot, r odd = "B" slot.
    int   dst[4];
    float inv[4];
    uint32_t ah01[4], ah89[4], al01[4], al89[4];

#pragma unroll
    for (int r = 0; r < 4; r++) dst[r] = __ldcs(edge_dst + base + r * 8 + g8);

    if (FIRST) {
#pragma unroll
        for (int r = 0; r < 4; r++) {
            const int e = base + r * 8 + g8;
            const float2* p = (const float2*)(cav_in + (size_t)e * QQ);
            float2 v0 = __ldcs(p + i4);       // cols 2i4, 2i4+1
            float2 v1 = __ldcs(p + 4 + i4);   // cols 2i4+8, 2i4+9
            split2(v0.x, v0.y, ah01[r], al01[r]);
            split2(v1.x, v1.y, ah89[r], al89[r]);
            inv[r] = 1.0f;
        }
    } else {
        int src[4], jdx[4];
#pragma unroll
        for (int r = 0; r < 4; r++) {
            const int e = base + r * 8 + g8;
            src[r] = __ldcs(a1_src + e);
            jdx[r] = __ldcs(indice + e);
        }
        float4 m[4];
        uint2  t[4];
#pragma unroll
        for (int r = 0; r < 4; r++) {
            m[r] = __ldg((const float4*)(marg + (size_t)src[r] * QQ + 4 * i4));
            t[r] = *(const uint2*)(t2_cur + (size_t)jdx[r] * 8 + 2 * i4);
        }
#pragma unroll
        for (int r = 0; r < 4; r++) {
            float2 f0 = __half22float2(*(__half2*)&t[r].x);
            float2 f1 = __half22float2(*(__half2*)&t[r].y);
            float x0 = m[r].x - f0.x, x1 = m[r].y - f0.y;
            float x2 = m[r].z - f1.x, x3 = m[r].w - f1.y;
            float mx = fmaxf(fmaxf(x0, x1), fmaxf(x2, x3));
            mx = fmaxf(mx, __shfl_xor_sync(0xffffffffu, mx, 1));
            mx = fmaxf(mx, __shfl_xor_sync(0xffffffffu, mx, 2));
            x0 = __expf(x0 - mx); x1 = __expf(x1 - mx);
            x2 = __expf(x2 - mx); x3 = __expf(x3 - mx);
            float s = x0 + x1 + x2 + x3;
            s += __shfl_xor_sync(0xffffffffu, s, 1);
            s += __shfl_xor_sync(0xffffffffu, s, 2);
            inv[r] = 1.0f / s;
            split2(x0, x1, ah01[r], al01[r]);
            split2(x2, x3, ah89[r], al89[r]);
        }
    }

    // ---- Phase 2: MMAs + epilogue per tile ----
#define MMA(D, A0, A1, A2, A3, B0, B1) \
    asm volatile("mma.sync.aligned.m16n8k16.row.col.f32.f16.f16.f32 " \
                 "{%0,%1,%2,%3}, {%4,%5,%6,%7}, {%8,%9}, {%0,%1,%2,%3};" \
                 : "+f"(D[0]), "+f"(D[1]), "+f"(D[2]), "+f"(D[3]) \
                 : "r"(A0), "r"(A1), "r"(A2), "r"(A3), "r"(B0), "r"(B1))
#pragma unroll
    for (int T = 0; T < 2; T++) {
        const int rA = 2 * T, rB = 2 * T + 1;
        float d0[4] = {0.f, 0.f, 0.f, 0.f};
        float d1[4] = {0.f, 0.f, 0.f, 0.f};
        MMA(d0, ah01[rA], ah01[rB], ah89[rA], ah89[rB], bh0, bh1);
        MMA(d0, ah01[rA], ah01[rB], ah89[rA], ah89[rB], bl0, bl1);
        MMA(d0, al01[rA], al01[rB], al89[rA], al89[rB], bh0, bh1);
        MMA(d1, ah01[rA], ah01[rB], ah89[rA], ah89[rB], bh2, bh3);
        MMA(d1, ah01[rA], ah01[rB], ah89[rA], ah89[rB], bl2, bl3);
        MMA(d1, al01[rA], al01[rB], al89[rA], al89[rB], bh2, bh3);

        const int eA = base + rA * 8 + g8;
        const int eB = base + rB * 8 + g8;
        const float ivA = inv[rA], ivB = inv[rB];

        float oA0 = __logf(fmaf(d0[0], ivA, EPSV));   // col 2i4
        float oA1 = __logf(fmaf(d0[1], ivA, EPSV));   // col 2i4+1
        float oA2 = __logf(fmaf(d1[0], ivA, EPSV));   // col 2i4+8
        float oA3 = __logf(fmaf(d1[1], ivA, EPSV));   // col 2i4+9
        float oB0 = __logf(fmaf(d0[2], ivB, EPSV));
        float oB1 = __logf(fmaf(d0[3], ivB, EPSV));
        float oB2 = __logf(fmaf(d1[2], ivB, EPSV));
        float oB3 = __logf(fmaf(d1[3], ivB, EPSV));

        if (!LAST) {
            uint2 vA, vB;
            vA.x = pack_h2(oA0, oA1); vA.y = pack_h2(oA2, oA3);
            vB.x = pack_h2(oB0, oB1); vB.y = pack_h2(oB2, oB3);
            *(uint2*)(t2_next + (size_t)eA * 8 + 2 * i4) = vA;
            *(uint2*)(t2_next + (size_t)eB * 8 + 2 * i4) = vB;
        }

        asm volatile("red.global.add.v4.f32 [%0], {%1,%2,%3,%4};"
                     :: "l"(accum + (size_t)dst[rA] * QQ + 4 * i4),
                        "f"(oA0), "f"(oA1), "f"(oA2), "f"(oA3) : "memory");
        asm volatile("red.global.add.v4.f32 [%0], {%1,%2,%3,%4};"
                     :: "l"(accum + (size_t)dst[rB] * QQ + 4 * i4),
                        "f"(oB0), "f"(oB1), "f"(oB2), "f"(oB3) : "memory");
    }
#undef MMA
}

// seed all 5 accumulators with permuted field (one launch)
__global__ void __launch_bounds__(256)
seed_kernel(const float* __restrict__ field, float* __restrict__ acc)
{
    const int n = blockIdx.x * blockDim.x + threadIdx.x;
    if (n >= NN) return;
    const float4* fp = (const float4*)(field + (size_t)n * QQ);
    float4 v[4] = {fp[0], fp[1], fp[2], fp[3]};
    const float* x = (const float*)v;
    float y[QQ];
#pragma unroll
    for (int p = 0; p < QQ; p++) y[p] = x[permcol(p)];
#pragma unroll
    for (int b = 0; b < 5; b++) {
        float4* op = (float4*)(acc + (size_t)b * NN * QQ + (size_t)n * QQ);
#pragma unroll
        for (int g = 0; g < 4; g++) op[g] = ((float4*)y)[g];
    }
}

// out = log_softmax(marg) — read permuted, write natural order
__global__ void __launch_bounds__(256)
out_kernel(const float* __restrict__ marg, float* __restrict__ out)
{
    const int n = blockIdx.x * blockDim.x + threadIdx.x;
    if (n >= NN) return;
    const float4* mp = (const float4*)(marg + (size_t)n * QQ);
    float4 v[4] = {mp[0], mp[1], mp[2], mp[3]};
    const float* x = (const float*)v;
    float mx = x[0];
#pragma unroll
    for (int p = 1; p < QQ; p++) mx = fmaxf(mx, x[p]);
    float s = 0.0f;
#pragma unroll
    for (int p = 0; p < QQ; p++) s += __expf(x[p] - mx);
    const float lse = mx + __logf(s);
    float y[QQ];
#pragma unroll
    for (int p = 0; p < QQ; p++) y[permcol(p)] = x[p] - lse;
    float4* op = (float4*)(out + (size_t)n * QQ);
#pragma unroll
    for (int g = 0; g < 4; g++) op[g] = ((float4*)y)[g];
}

extern "C" void kernel_launch(void* const* d_in, const int* in_sizes, int n_in,
                              void* d_out, int out_size)
{
    // metadata order: marg_i(unused), cav_ij, C, field_i, edge_dst, a1_src, indice_ij
    const float* cav_ij   = (const float*)d_in[1];
    const float* Cmat     = (const float*)d_in[2];
    const float* field_i  = (const float*)d_in[3];
    const int*   edge_dst = (const int*)d_in[4];
    const int*   a1_src   = (const int*)d_in[5];
    const int*   indice   = (const int*)d_in[6];
    float*       out      = (float*)d_out;

    float* acc;
    __half2 *t2a, *t2b;
    cudaGetSymbolAddress((void**)&acc, g_acc);
    cudaGetSymbolAddress((void**)&t2a, g_t2a);
    cudaGetSymbolAddress((void**)&t2b, g_t2b);
    float* a0 = acc;
    float* a1 = acc + (size_t)1 * NN * QQ;
    float* a2 = acc + (size_t)2 * NN * QQ;
    float* a3 = acc + (size_t)3 * NN * QQ;
    float* a4 = acc + (size_t)4 * NN * QQ;

    const int EB = 256;
    const int EG = EE / EB;              // 6250 exact
    const int NG = (NN + 255) / 256;

    seed_kernel<<<NG, 256>>>(field_i, acc);

    edge_kernel<true,  false><<<EG, EB>>>(cav_ij, nullptr, nullptr, t2a,
                                          a1_src, indice, edge_dst, Cmat, a0);
    edge_kernel<false, false><<<EG, EB>>>(nullptr, a0, t2a, t2b,
                                          a1_src, indice, edge_dst, Cmat, a1);
    edge_kernel<false, false><<<EG, EB>>>(nullptr, a1, t2b, t2a,
                                          a1_src, indice, edge_dst, Cmat, a2);
    edge_kernel<false, false><<<EG, EB>>>(nullptr, a2, t2a, t2b,
                                          a1_src, indice, edge_dst, Cmat, a3);
    edge_kernel<false, true ><<<EG, EB>>>(nullptr, a3, t2b, nullptr,
                                          a1_src, indice, edge_dst, Cmat, a4);

    out_kernel<<<NG, 256>>>(a4, out);
}

// round 10
// speedup vs baseline: 1.7878x; 1.0061x over previous
#include <cuda_runtime.h>
#include <cuda_fp16.h>
#include <cstddef>
#include <cstdint>

#define NN 50000
#define EE 1600000
#define QQ 16
#define EPSV 1e-8f

// Scratch (allocation-free rule: __device__ globals)
// temp2 stored as fp16 in fragment-permuted col order: 32 B per edge.
__device__ __align__(16) __half2 g_t2a[(size_t)EE * 8];
__device__ __align__(16) __half2 g_t2b[(size_t)EE * 8];
__device__ float g_acc[5][NN * QQ];          // 5 pre-seeded accumulators (permuted)
__device__ __align__(16) uint32_t g_cfrag[32 * 8];  // per-lane split-C fragments

// permuted position p  <->  natural column
__host__ __device__ constexpr int permcol(int p) {
    return 2 * (p >> 2) + (p & 1) + 8 * ((p >> 1) & 1);
}

__device__ __forceinline__ uint32_t pack_h2(float a, float b) {
    __half2 h = __floats2half2_rn(a, b);
    uint32_t u;
    asm("mov.b32 %0, %1;" : "=r"(u) : "r"(*(uint32_t*)&h));
    return u;
}

__device__ __forceinline__ void split_f16(float x, float& hi, float& lo) {
    __half h = __float2half_rn(x);
    hi = __half2float(h);
    lo = x - hi;
}

// packed split of a float pair: hi2 = fp16x2(x0,x1); lo2 = fp16x2(residuals)
__device__ __forceinline__ void split2(float x0, float x1,
                                       uint32_t& hi2, uint32_t& lo2) {
    hi2 = pack_h2(x0, x1);
    __half2 h = *(__half2*)&hi2;
    float2 hf = __half22float2(h);
    lo2 = pack_h2(x0 - hf.x, x1 - hf.y);
}

// one warp: build per-lane split-C fragment table (verified R7/R8 mapping)
__global__ void cfrag_kernel(const float* __restrict__ Cmat,
                             uint32_t* __restrict__ tab)
{
    const int lane = threadIdx.x;
    if (lane >= 32) return;
    const int i4 = lane & 3;
    const int g8 = lane >> 2;
    const int k0 = 2 * i4;
    uint32_t v[8];
    float h00,l00,h01,l01,h10,l10,h11,l11;
#pragma unroll
    for (int nb = 0; nb < 2; nb++) {
        const int n = nb * 8 + g8;
        split_f16(Cmat[(k0    ) * QQ + n], h00, l00);
        split_f16(Cmat[(k0 + 1) * QQ + n], h01, l01);
        split_f16(Cmat[(k0 + 8) * QQ + n], h10, l10);
        split_f16(Cmat[(k0 + 9) * QQ + n], h11, l11);
        v[2*nb + 0] = pack_h2(h00, h01);   // bh(2nb)
        v[2*nb + 1] = pack_h2(h10, h11);   // bh(2nb+1)
        v[4 + 2*nb + 0] = pack_h2(l00, l01); // bl(2nb)
        v[4 + 2*nb + 1] = pack_h2(l10, l11); // bl(2nb+1)
    }
    uint4* tp = (uint4*)(tab + lane * 8);
    tp[0] = make_uint4(v[0], v[1], v[2], v[3]);   // bh0..bh3
    tp[1] = make_uint4(v[4], v[5], v[6], v[7]);   // bl0..bl3
}

// ---------------------------------------------------------------------------
// Fused edge kernel: quad-cooperative rows, fragment-direct, no smem.
// 4 lanes (i4 = lane&3) own one edge row; lane holds natural cols
// {2i4, 2i4+1, 2i4+8, 2i4+9} = its m16n8k16 A-fragment slots.
// B fragments come from the precomputed table (2x LDG.128, L2-hot).
// Precision: split-fp16 Markidis (Ah*Ch + Ah*Cl + Al*Ch, fp32 accum).
// ---------------------------------------------------------------------------
template <bool FIRST, bool LAST>
__global__ void __launch_bounds__(256, 5)
edge_kernel(const float* __restrict__ cav_in,
            const float* __restrict__ marg,      // permuted
            const __half2* __restrict__ t2_cur,  // permuted
            __half2* __restrict__ t2_next,       // permuted
            const int* __restrict__ a1_src,
            const int* __restrict__ indice,
            const int* __restrict__ edge_dst,
            const uint32_t* __restrict__ cfrag,
            float* __restrict__ accum)           // permuted
{
    const int lane = threadIdx.x & 31;
    const int i4   = lane & 3;
    const int g8   = lane >> 2;
    const int base = blockIdx.x * 256 + (threadIdx.x >> 5) * 32;

    // ---- B fragments from table ----
    const uint4* tp = (const uint4*)(cfrag + lane * 8);
    const uint4 bh = __ldg(tp);
    const uint4 bl = __ldg(tp + 1);

#define MMA(D, A0, A1, A2, A3, B0, B1) \
    asm volatile("mma.sync.aligned.m16n8k16.row.col.f32.f16.f16.f32 " \
                 "{%0,%1,%2,%3}, {%4,%5,%6,%7}, {%8,%9}, {%0,%1,%2,%3};" \
                 : "+f"(D[0]), "+f"(D[1]), "+f"(D[2]), "+f"(D[3]) \
                 : "r"(A0), "r"(A1), "r"(A2), "r"(A3), "r"(B0), "r"(B1))

#pragma unroll
    for (int T = 0; T < 2; T++) {
        const int eA = base + T * 16 + g8;
        const int eB = eA + 8;
        const int dstA = __ldcs(edge_dst + eA);
        const int dstB = __ldcs(edge_dst + eB);

        float xA[4], xB[4];
        float invA = 1.0f, invB = 1.0f;

        if (FIRST) {
            const float2* pA = (const float2*)(cav_in + (size_t)eA * QQ);
            const float2* pB = (const float2*)(cav_in + (size_t)eB * QQ);
            float2 a0 = __ldcs(pA + i4);
            float2 a1 = __ldcs(pA + 4 + i4);
            float2 b0 = __ldcs(pB + i4);
            float2 b1 = __ldcs(pB + 4 + i4);
            xA[0]=a0.x; xA[1]=a0.y; xA[2]=a1.x; xA[3]=a1.y;
            xB[0]=b0.x; xB[1]=b0.y; xB[2]=b1.x; xB[3]=b1.y;
        } else {
            const int sA = __ldcs(a1_src + eA), sB = __ldcs(a1_src + eB);
            const int jA = __ldcs(indice + eA), jB = __ldcs(indice + eB);
            float4 mA = __ldg((const float4*)(marg + (size_t)sA * QQ + 4 * i4));
            float4 mB = __ldg((const float4*)(marg + (size_t)sB * QQ + 4 * i4));
            uint2 ta = *(const uint2*)(t2_cur + (size_t)jA * 8 + 2 * i4);
            uint2 tb = *(const uint2*)(t2_cur + (size_t)jB * 8 + 2 * i4);
            float2 fa0 = __half22float2(*(__half2*)&ta.x);
            float2 fa1 = __half22float2(*(__half2*)&ta.y);
            float2 fb0 = __half22float2(*(__half2*)&tb.x);
            float2 fb1 = __half22float2(*(__half2*)&tb.y);
            xA[0]=mA.x-fa0.x; xA[1]=mA.y-fa0.y; xA[2]=mA.z-fa1.x; xA[3]=mA.w-fa1.y;
            xB[0]=mB.x-fb0.x; xB[1]=mB.y-fb0.y; xB[2]=mB.z-fb1.x; xB[3]=mB.w-fb1.y;

            float mxA = fmaxf(fmaxf(xA[0], xA[1]), fmaxf(xA[2], xA[3]));
            float mxB = fmaxf(fmaxf(xB[0], xB[1]), fmaxf(xB[2], xB[3]));
            mxA = fmaxf(mxA, __shfl_xor_sync(0xffffffffu, mxA, 1));
            mxA = fmaxf(mxA, __shfl_xor_sync(0xffffffffu, mxA, 2));
            mxB = fmaxf(mxB, __shfl_xor_sync(0xffffffffu, mxB, 1));
            mxB = fmaxf(mxB, __shfl_xor_sync(0xffffffffu, mxB, 2));
            float sAs = 0.f, sBs = 0.f;
#pragma unroll
            for (int q = 0; q < 4; q++) {
                xA[q] = __expf(xA[q] - mxA); sAs += xA[q];
                xB[q] = __expf(xB[q] - mxB); sBs += xB[q];
            }
            sAs += __shfl_xor_sync(0xffffffffu, sAs, 1);
            sAs += __shfl_xor_sync(0xffffffffu, sAs, 2);
            sBs += __shfl_xor_sync(0xffffffffu, sBs, 1);
            sBs += __shfl_xor_sync(0xffffffffu, sBs, 2);
            invA = 1.0f / sAs;
            invB = 1.0f / sBs;
        }

        // A fragments in registers (hi/lo split)
        uint32_t ah0, ah1, ah2, ah3, al0, al1, al2, al3;
        split2(xA[0], xA[1], ah0, al0);
        split2(xA[2], xA[3], ah2, al2);
        split2(xB[0], xB[1], ah1, al1);
        split2(xB[2], xB[3], ah3, al3);

        float d0[4] = {0.f, 0.f, 0.f, 0.f};
        float d1[4] = {0.f, 0.f, 0.f, 0.f};
        MMA(d0, ah0, ah1, ah2, ah3, bh.x, bh.y);
        MMA(d0, ah0, ah1, ah2, ah3, bl.x, bl.y);
        MMA(d0, al0, al1, al2, al3, bh.x, bh.y);
        MMA(d1, ah0, ah1, ah2, ah3, bh.z, bh.w);
        MMA(d1, ah0, ah1, ah2, ah3, bl.z, bl.w);
        MMA(d1, al0, al1, al2, al3, bh.z, bh.w);

        float oA0 = __logf(fmaf(d0[0], invA, EPSV));   // col 2i4
        float oA1 = __logf(fmaf(d0[1], invA, EPSV));   // col 2i4+1
        float oA2 = __logf(fmaf(d1[0], invA, EPSV));   // col 2i4+8
        float oA3 = __logf(fmaf(d1[1], invA, EPSV));   // col 2i4+9
        float oB0 = __logf(fmaf(d0[2], invB, EPSV));
        float oB1 = __logf(fmaf(d0[3], invB, EPSV));
        float oB2 = __logf(fmaf(d1[2], invB, EPSV));
        float oB3 = __logf(fmaf(d1[3], invB, EPSV));

        if (!LAST) {
            uint2 vA, vB;
            vA.x = pack_h2(oA0, oA1); vA.y = pack_h2(oA2, oA3);
            vB.x = pack_h2(oB0, oB1); vB.y = pack_h2(oB2, oB3);
            *(uint2*)(t2_next + (size_t)eA * 8 + 2 * i4) = vA;
            *(uint2*)(t2_next + (size_t)eB * 8 + 2 * i4) = vB;
        }

        asm volatile("red.global.add.v4.f32 [%0], {%1,%2,%3,%4};"
                     :: "l"(accum + (size_t)dstA * QQ + 4 * i4),
                        "f"(oA0), "f"(oA1), "f"(oA2), "f"(oA3) : "memory");
        asm volatile("red.global.add.v4.f32 [%0], {%1,%2,%3,%4};"
                     :: "l"(accum + (size_t)dstB * QQ + 4 * i4),
                        "f"(oB0), "f"(oB1), "f"(oB2), "f"(oB3) : "memory");
    }
#undef MMA
}

// seed all 5 accumulators with permuted field (one launch)
__global__ void __launch_bounds__(256)
seed_kernel(const float* __restrict__ field, float* __restrict__ acc)
{
    const int n = blockIdx.x * blockDim.x + threadIdx.x;
    if (n >= NN) return;
    const float4* fp = (const float4*)(field + (size_t)n * QQ);
    float4 v[4] = {fp[0], fp[1], fp[2], fp[3]};
    const float* x = (const float*)v;
    float y[QQ];
#pragma unroll
    for (int p = 0; p < QQ; p++) y[p] = x[permcol(p)];
#pragma unroll
    for (int b = 0; b < 5; b++) {
        float4* op = (float4*)(acc + (size_t)b * NN * QQ + (size_t)n * QQ);
#pragma unroll
        for (int g = 0; g < 4; g++) op[g] = ((float4*)y)[g];
    }
}

// out = log_softmax(marg) — read permuted, write natural order
__global__ void __launch_bounds__(256)
out_kernel(const float* __restrict__ marg, float* __restrict__ out)
{
    const int n = blockIdx.x * blockDim.x + threadIdx.x;
    if (n >= NN) return;
    const float4* mp = (const float4*)(marg + (size_t)n * QQ);
    float4 v[4] = {mp[0], mp[1], mp[2], mp[3]};
    const float* x = (const float*)v;
    float mx = x[0];
#pragma unroll
    for (int p = 1; p < QQ; p++) mx = fmaxf(mx, x[p]);
    float s = 0.0f;
#pragma unroll
    for (int p = 0; p < QQ; p++) s += __expf(x[p] - mx);
    const float lse = mx + __logf(s);
    float y[QQ];
#pragma unroll
    for (int p = 0; p < QQ; p++) y[permcol(p)] = x[p] - lse;
    float4* op = (float4*)(out + (size_t)n * QQ);
#pragma unroll
    for (int g = 0; g < 4; g++) op[g] = ((float4*)y)[g];
}

extern "C" void kernel_launch(void* const* d_in, const int* in_sizes, int n_in,
                              void* d_out, int out_size)
{
    // metadata order: marg_i(unused), cav_ij, C, field_i, edge_dst, a1_src, indice_ij
    const float* cav_ij   = (const float*)d_in[1];
    const float* Cmat     = (const float*)d_in[2];
    const float* field_i  = (const float*)d_in[3];
    const int*   edge_dst = (const int*)d_in[4];
    const int*   a1_src   = (const int*)d_in[5];
    const int*   indice   = (const int*)d_in[6];
    float*       out      = (float*)d_out;

    float* acc;
    __half2 *t2a, *t2b;
    uint32_t* cfrag;
    cudaGetSymbolAddress((void**)&acc,   g_acc);
    cudaGetSymbolAddress((void**)&t2a,   g_t2a);
    cudaGetSymbolAddress((void**)&t2b,   g_t2b);
    cudaGetSymbolAddress((void**)&cfrag, g_cfrag);
    float* a0 = acc;
    float* a1 = acc + (size_t)1 * NN * QQ;
    float* a2 = acc + (size_t)2 * NN * QQ;
    float* a3 = acc + (size_t)3 * NN * QQ;
    float* a4 = acc + (size_t)4 * NN * QQ;

    const int EB = 256;
    const int EG = EE / EB;              // 6250 exact
    const int NG = (NN + 255) / 256;

    cfrag_kernel<<<1, 32>>>(Cmat, cfrag);
    seed_kernel<<<NG, 256>>>(field_i, acc);

    edge_kernel<true,  false><<<EG, EB>>>(cav_ij, nullptr, nullptr, t2a,
                                          a1_src, indice, edge_dst, cfrag, a0);
    edge_kernel<false, false><<<EG, EB>>>(nullptr, a0, t2a, t2b,
                                          a1_src, indice, edge_dst, cfrag, a1);
    edge_kernel<false, false><<<EG, EB>>>(nullptr, a1, t2b, t2a,
                                          a1_src, indice, edge_dst, cfrag, a2);
    edge_kernel<false, false><<<EG, EB>>>(nullptr, a2, t2a, t2b,
                                          a1_src, indice, edge_dst, cfrag, a3);
    edge_kernel<false, true ><<<EG, EB>>>(nullptr, a3, t2b, nullptr,
                                          a1_src, indice, edge_dst, cfrag, a4);

    out_kernel<<<NG, 256>>>(a4, out);
}